// round 16
// baseline (speedup 1.0000x reference)
#include <cuda_runtime.h>
#include <cuda_fp16.h>

#define B_  256
#define C_  1152
#define N_  10
#define ND_ 160          // N_*D_
#define CCH_ 144         // k1 c-chunks of 8
#define QCH_ 4           // routing c-chunks of 288

// u_hat scratch (fp16), per (b,c) p-layout: [g(0..1)][n(0..9)][8]; d = g*8+dd
__device__ unsigned short g_uhat[(size_t)256*1152*160];
// s0 accumulator (P-LAYOUT), atomically accumulated by k1: [b][160]
__device__ float g_s0[(size_t)B_*ND_];
// routing per-chunk partial s: [qchunk(4)][b][160] PLAIN layout (two buffers)
__device__ float g_sp [(size_t)QCH_*256*160];
__device__ float g_sp2[(size_t)QCH_*256*160];
// v1 per b, PLAIN layout
__device__ float g_v[(size_t)256*160];

// ---------------------------------------------------------------------------
// K_zero: clear g_s0 before k1's atomic accumulation.
// ---------------------------------------------------------------------------
__global__ void k_zero()
{
    int i = blockIdx.x*blockDim.x + threadIdx.x;
    if (i < B_*ND_) g_s0[i] = 0.f;
}

// ---------------------------------------------------------------------------
// K1: u_hat[b,n,c,d] = sum_i W[n,c,d,i]*x[b,c,i]
// grid (144 c-chunks of 8, 4 b-chunks of 64), 320 threads.
// s0 partials now accumulated via atomicAdd into tiny g_s0 (L2-resident),
// keeping the chip-wide working set (u_hat) inside L2.
// ---------------------------------------------------------------------------
__global__ __launch_bounds__(320, 3) void k1_gemm(const float* __restrict__ x,
                                                  const float* __restrict__ W)
{
    __shared__ float xs[64*64];                         // 16 KB
    __shared__ alignas(16) unsigned short usm[8*8*168]; // 21 KB: [bl][cl][168 pad]

    const int t    = threadIdx.x;
    const int n    = t >> 5;          // warp id = output capsule
    const int lane = t & 31;
    const int q    = lane >> 3;       // d-quarter 0..3
    const int cl   = lane & 7;        // c within block
    const int c    = blockIdx.x * 8 + cl;
    const int b0   = blockIdx.y * 64;

    float Wr[32];
    {
        const float4* Wp = reinterpret_cast<const float4*>(
            W + ((size_t)(n*C_ + c))*128 + q*32);
#pragma unroll
        for (int k = 0; k < 8; ++k) {
            float4 f = Wp[k];
            Wr[4*k]=f.x; Wr[4*k+1]=f.y; Wr[4*k+2]=f.z; Wr[4*k+3]=f.w;
        }
    }

    for (int idx = t; idx < 1024; idx += 320) {
        int bl = idx >> 4;
        int r  = idx & 15;
        reinterpret_cast<float4*>(xs)[bl*16 + r] =
            reinterpret_cast<const float4*>(
                x + (size_t)(b0 + bl)*(C_*8) + blockIdx.x*64)[r];
    }
    __syncthreads();

    const int poff = (q>>1)*80 + n*8 + (q&1)*4;

    for (int bg = 0; bg < 8; ++bg) {
        const int b_base = b0 + bg*8;

#pragma unroll
        for (int bl = 0; bl < 8; ++bl) {
            const float4* xr = reinterpret_cast<const float4*>(
                xs + (bg*8 + bl)*64 + cl*8);
            float4 f0 = xr[0], f1 = xr[1];
            float xv[8];
            xv[0]=f0.x; xv[1]=f0.y; xv[2]=f0.z; xv[3]=f0.w;
            xv[4]=f1.x; xv[5]=f1.y; xv[6]=f1.z; xv[7]=f1.w;

            float u[4];
#pragma unroll
            for (int dd = 0; dd < 4; ++dd) {
                float a = 0.f;
#pragma unroll
                for (int i = 0; i < 8; ++i) a = fmaf(Wr[dd*8+i], xv[i], a);
                u[dd] = a;
            }

            __half2 h01 = __floats2half2_rn(u[0], u[1]);
            __half2 h23 = __floats2half2_rn(u[2], u[3]);
            uint2 val;
            val.x = *reinterpret_cast<unsigned int*>(&h01);
            val.y = *reinterpret_cast<unsigned int*>(&h23);
            *reinterpret_cast<uint2*>(usm + (bl*8 + cl)*168 + poff) = val;
        }
        __syncthreads();

        // coalesced u_hat sweep: 8 b x 8 c x 160 halfs = 1280 uint4
#pragma unroll
        for (int it = 0; it < 4; ++it) {
            int j   = it*320 + t;
            int bl2 = j / 160;
            int r   = j - bl2*160;
            int cL  = r / 20;
            int h   = r - cL*20;
            uint4 v = *reinterpret_cast<const uint4*>(usm + (bl2*8 + cL)*168 + h*8);
            *reinterpret_cast<uint4*>(
                g_uhat + (size_t)(b_base + bl2)*(C_*160)
                       + (size_t)(blockIdx.x*8 + cL)*160 + h*8) = v;
        }

        // s0: sum staged tile over 8 c's, atomically add to g_s0 (p-layout)
#pragma unroll
        for (int rr = 0; rr < 2; ++rr) {
            int task = rr*320 + t;         // 0..639
            int bl2  = task / 80;
            int pos2 = task - bl2*80;
            float ax = 0.f, ay = 0.f;
#pragma unroll
            for (int cc = 0; cc < 8; ++cc) {
                __half2 h = *reinterpret_cast<const __half2*>(
                    usm + (bl2*8 + cc)*168 + pos2*2);
                float2 f = __half22float2(h);
                ax += f.x; ay += f.y;
            }
            float* dst = g_s0 + (size_t)(b_base + bl2)*ND_ + pos2*2;
            atomicAdd(dst,     ax);
            atomicAdd(dst + 1, ay);
        }
        __syncthreads();
    }
}

// ---------------------------------------------------------------------------
// K_red_s0: v1 = squash(0.1 * g_s0). grid 256, 160 threads.
// Input p-layout, output PLAIN layout.
// ---------------------------------------------------------------------------
__global__ __launch_bounds__(160) void k_red_s0()
{
    __shared__ float sm[ND_];
    const int b = blockIdx.x;
    const int t = threadIdx.x;

    float s = g_s0[(size_t)b*ND_ + t] * 0.1f;
    sm[t] = s;
    __syncthreads();

    const int g2 = t / 80, rem = t - g2*80, nn = rem >> 3, dd = rem & 7;
    float sq = 0.f;
#pragma unroll
    for (int gg = 0; gg < 2; ++gg)
#pragma unroll
        for (int d2 = 0; d2 < 8; ++d2) {
            float v = sm[gg*80 + nn*8 + d2]; sq += v*v;
        }
    float f = sq / (1.f + sq) / (sqrtf(sq) + 1e-8f);
    g_v[(size_t)b*ND_ + nn*16 + g2*8 + dd] = s * f;   // plain layout
}

// ---------------------------------------------------------------------------
// K_red_out: v = squash(sum of 4 pass-2 partials) -> out. grid 256, 160 thr.
// ---------------------------------------------------------------------------
__global__ __launch_bounds__(160) void k_red_out(float* __restrict__ out)
{
    const int b = blockIdx.x;
    const int t = threadIdx.x;

    float s = 0.f;
#pragma unroll
    for (int k = 0; k < QCH_; ++k)
        s += g_sp2[((size_t)k*B_ + b)*ND_ + t];

    float sq = s*s;
#pragma unroll
    for (int o = 1; o < 16; o <<= 1)
        sq += __shfl_xor_sync(0xffffffffu, sq, o);
    float f = sq / (1.f + sq) / (sqrtf(sq) + 1e-8f);
    out[(size_t)b*ND_ + t] = s * f;
}

// ---------------------------------------------------------------------------
// K2 pass (unchanged from R14): one routing iteration over a 288-c chunk.
//   PASS 1: vcur = v1.   PASS 2: vcur = v1 + v2 (prologue). logit = u.vcur.
// grid (4 qchunks, 256 b), 256 threads = 8 warps, 4 CTAs/SM.
// lane = g*16+n: g = d-half, n = capsule; 2 chains (c = 2w, 2w+1), 18 iters.
// ---------------------------------------------------------------------------
__device__ __forceinline__ void route_step(
    uint4 X, bool act,
    const __half2* __restrict__ vh2, float* __restrict__ sacc)
{
    unsigned int r[4] = {X.x, X.y, X.z, X.w};
    const __half2* u2 = reinterpret_cast<const __half2*>(r);

    __half2 acc = __hmul2(u2[0], vh2[0]);
    acc = __hfma2(u2[1], vh2[1], acc);
    acc = __hfma2(u2[2], vh2[2], acc);
    acc = __hfma2(u2[3], vh2[3], acc);
    float2 fa = __half22float2(acc);
    float part = fa.x + fa.y;
    float logit = part + __shfl_xor_sync(0xffffffffu, part, 16);

    float e = act ? __expf(logit) : 0.f;
    float ssum = e;
#pragma unroll
    for (int o = 8; o; o >>= 1)
        ssum += __shfl_xor_sync(0xffffffffu, ssum, o);
    float coef = e * __fdividef(1.f, ssum);

#pragma unroll
    for (int k = 0; k < 4; ++k) {
        float2 f = __half22float2(u2[k]);
        sacc[2*k]   = fmaf(coef, f.x, sacc[2*k]);
        sacc[2*k+1] = fmaf(coef, f.y, sacc[2*k+1]);
    }
}

template<int PASS>
__global__ __launch_bounds__(256, 4) void k2_pass()
{
    __shared__ float sred[8*ND_];
    __shared__ float vsm[ND_];

    const int  qc = blockIdx.x;
    const int  b  = blockIdx.y;
    const int  t  = threadIdx.x;
    const int  w  = t >> 5;
    const int  l  = t & 31;
    const int  g  = l >> 4;
    const int  n  = l & 15;
    const bool act = (n < N_);

    if (t < ND_) {
        if (PASS == 1) {
            vsm[t] = g_v[(size_t)b*ND_ + t];
        } else {
            float s = 0.f;
#pragma unroll
            for (int k = 0; k < QCH_; ++k)
                s += g_sp[((size_t)k*B_ + b)*ND_ + t];
            float sq = s*s;
#pragma unroll
            for (int o = 1; o < 16; o <<= 1)
                sq += __shfl_xor_sync(0xffffffffu, sq, o);
            float f = sq / (1.f + sq) / (sqrtf(sq) + 1e-8f);
            vsm[t] = s * f + g_v[(size_t)b*ND_ + t];    // v1 + v2
        }
    }
    __syncthreads();

    __half2 vh2[4];
#pragma unroll
    for (int k = 0; k < 4; ++k) {
        float vx = act ? vsm[n*16 + g*8 + 2*k]     : 0.f;
        float vy = act ? vsm[n*16 + g*8 + 2*k + 1] : 0.f;
        vh2[k] = __floats2half2_rn(vx, vy);
    }

    float sacc[8];
#pragma unroll
    for (int d = 0; d < 8; ++d) sacc[d] = 0.f;

    const unsigned short* uhA =
        g_uhat + (size_t)b*(C_*160) + (size_t)(qc*288 + 2*w)*160 + g*80 + n*8;
    const unsigned short* uhB = uhA + 160;

    uint4 A, Bv;
    if (act) {
        A  = *reinterpret_cast<const uint4*>(uhA);
        Bv = *reinterpret_cast<const uint4*>(uhB);
    }

    for (int i = 0; i < 18; ++i) {
        uint4 a = A;
        if (i < 17 && act)
            A = *reinterpret_cast<const uint4*>(uhA + (size_t)(i+1)*16*160);
        route_step(a, act, vh2, sacc);

        uint4 bb = Bv;
        if (i < 17 && act)
            Bv = *reinterpret_cast<const uint4*>(uhB + (size_t)(i+1)*16*160);
        route_step(bb, act, vh2, sacc);
    }

    if (act) {
#pragma unroll
        for (int d = 0; d < 8; ++d) sred[w*ND_ + n*16 + g*8 + d] = sacc[d];
    }
    __syncthreads();
    if (t < ND_) {
        float a = 0.f;
#pragma unroll
        for (int k = 0; k < 8; ++k) a += sred[k*ND_ + t];
        float* dst = (PASS == 1) ? g_sp : g_sp2;
        dst[((size_t)qc*B_ + b)*ND_ + t] = a;
    }
}

// ---------------------------------------------------------------------------
extern "C" void kernel_launch(void* const* d_in, const int* in_sizes, int n_in,
                              void* d_out, int out_size)
{
    const float* x;
    const float* W;
    if (in_sizes[0] == B_*C_*8) { x = (const float*)d_in[0]; W = (const float*)d_in[1]; }
    else                        { x = (const float*)d_in[1]; W = (const float*)d_in[0]; }
    float* out = (float*)d_out;

    k_zero<<<(B_*ND_ + 1023)/1024, 1024>>>();      // clear s0 accumulator
    k1_gemm<<<dim3(CCH_, 4), 320>>>(x, W);
    k_red_s0<<<B_, 160>>>();                       // g_s0 -> v1
    k2_pass<1><<<dim3(QCH_, B_), 256>>>();         // logit=u.v1 -> partial s (g_sp)
    k2_pass<2><<<dim3(QCH_, B_), 256>>>();         // logit=u.(v1+v2) -> g_sp2
    k_red_out<<<B_, 160>>>(out);                   // -> v3 = output
}

// round 17
// speedup vs baseline: 1.2135x; 1.2135x over previous
#include <cuda_runtime.h>
#include <cuda_fp16.h>

#define B_  256
#define C_  1152
#define N_  10
#define ND_ 160          // N_*D_
#define CCH_ 144         // k1 c-chunks of 8
#define QCH_ 4           // routing c-chunks of 288

// u_hat scratch (fp16), per (b,c) p-layout: [g(0..1)][n(0..9)][8]; d = g*8+dd
__device__ unsigned short g_uhat[(size_t)256*1152*160];
// s0 accumulator (P-LAYOUT), atomically accumulated by k1: [b][160]
__device__ float g_s0[(size_t)B_*ND_];
// routing per-chunk partial s: [qchunk(4)][b][160] PLAIN layout (two buffers)
__device__ float g_sp [(size_t)QCH_*256*160];
__device__ float g_sp2[(size_t)QCH_*256*160];
// v1 per b, PLAIN layout (written by pass1 prologue)
__device__ float g_v[(size_t)256*160];

// ---------------------------------------------------------------------------
// K_zero: clear g_s0 before k1's atomic accumulation.
// ---------------------------------------------------------------------------
__global__ void k_zero()
{
    int i = blockIdx.x*blockDim.x + threadIdx.x;
    if (i < B_*ND_) g_s0[i] = 0.f;
}

// ---------------------------------------------------------------------------
// K1: u_hat[b,n,c,d] = sum_i W[n,c,d,i]*x[b,c,i]
// grid (144 c-chunks of 8, 2 b-chunks of 128) = 288 CTAs -> SINGLE WAVE @occ3.
// 320 threads: warp = n, lane>>3 = q (d-quarter), lane&7 = c_local.
// x staged in two 64-b halves; u_hat staged through smem -> coalesced STG.128.
// ---------------------------------------------------------------------------
__global__ __launch_bounds__(320, 3) void k1_gemm(const float* __restrict__ x,
                                                  const float* __restrict__ W)
{
    __shared__ float xs[64*64];                         // 16 KB (64-b half)
    __shared__ alignas(16) unsigned short usm[8*8*168]; // 21 KB: [bl][cl][168 pad]

    const int t    = threadIdx.x;
    const int n    = t >> 5;          // warp id = output capsule
    const int lane = t & 31;
    const int q    = lane >> 3;       // d-quarter 0..3
    const int cl   = lane & 7;        // c within block
    const int c    = blockIdx.x * 8 + cl;
    const int b0   = blockIdx.y * 128;

    float Wr[32];
    {
        const float4* Wp = reinterpret_cast<const float4*>(
            W + ((size_t)(n*C_ + c))*128 + q*32);
#pragma unroll
        for (int k = 0; k < 8; ++k) {
            float4 f = Wp[k];
            Wr[4*k]=f.x; Wr[4*k+1]=f.y; Wr[4*k+2]=f.z; Wr[4*k+3]=f.w;
        }
    }

    // stage first 64-b half of x
    for (int idx = t; idx < 1024; idx += 320) {
        int bl = idx >> 4;
        int r  = idx & 15;
        reinterpret_cast<float4*>(xs)[bl*16 + r] =
            reinterpret_cast<const float4*>(
                x + (size_t)(b0 + bl)*(C_*8) + blockIdx.x*64)[r];
    }
    __syncthreads();

    const int poff = (q>>1)*80 + n*8 + (q&1)*4;

    for (int bg = 0; bg < 16; ++bg) {
        if (bg == 8) {
            // re-stage second 64-b half (prev iter ended with a sync)
            for (int idx = t; idx < 1024; idx += 320) {
                int bl = idx >> 4;
                int r  = idx & 15;
                reinterpret_cast<float4*>(xs)[bl*16 + r] =
                    reinterpret_cast<const float4*>(
                        x + (size_t)(b0 + 64 + bl)*(C_*8) + blockIdx.x*64)[r];
            }
            __syncthreads();
        }
        const int b_base = b0 + bg*8;

#pragma unroll
        for (int bl = 0; bl < 8; ++bl) {
            const float4* xr = reinterpret_cast<const float4*>(
                xs + (((bg & 7)*8) + bl)*64 + cl*8);
            float4 f0 = xr[0], f1 = xr[1];
            float xv[8];
            xv[0]=f0.x; xv[1]=f0.y; xv[2]=f0.z; xv[3]=f0.w;
            xv[4]=f1.x; xv[5]=f1.y; xv[6]=f1.z; xv[7]=f1.w;

            float u[4];
#pragma unroll
            for (int dd = 0; dd < 4; ++dd) {
                float a = 0.f;
#pragma unroll
                for (int i = 0; i < 8; ++i) a = fmaf(Wr[dd*8+i], xv[i], a);
                u[dd] = a;
            }

            __half2 h01 = __floats2half2_rn(u[0], u[1]);
            __half2 h23 = __floats2half2_rn(u[2], u[3]);
            uint2 val;
            val.x = *reinterpret_cast<unsigned int*>(&h01);
            val.y = *reinterpret_cast<unsigned int*>(&h23);
            *reinterpret_cast<uint2*>(usm + (bl*8 + cl)*168 + poff) = val;
        }
        __syncthreads();

        // coalesced u_hat sweep: 8 b x 8 c x 160 halfs = 1280 uint4
#pragma unroll
        for (int it = 0; it < 4; ++it) {
            int j   = it*320 + t;
            int bl2 = j / 160;
            int r   = j - bl2*160;
            int cL  = r / 20;
            int h   = r - cL*20;
            uint4 v = *reinterpret_cast<const uint4*>(usm + (bl2*8 + cL)*168 + h*8);
            *reinterpret_cast<uint4*>(
                g_uhat + (size_t)(b_base + bl2)*(C_*160)
                       + (size_t)(blockIdx.x*8 + cL)*160 + h*8) = v;
        }

        // s0: sum staged tile over 8 c's, atomically add to g_s0 (p-layout)
#pragma unroll
        for (int rr = 0; rr < 2; ++rr) {
            int task = rr*320 + t;         // 0..639
            int bl2  = task / 80;
            int pos2 = task - bl2*80;
            float ax = 0.f, ay = 0.f;
#pragma unroll
            for (int cc = 0; cc < 8; ++cc) {
                __half2 h = *reinterpret_cast<const __half2*>(
                    usm + (bl2*8 + cc)*168 + pos2*2);
                float2 f = __half22float2(h);
                ax += f.x; ay += f.y;
            }
            float* dst = g_s0 + (size_t)(b_base + bl2)*ND_ + pos2*2;
            atomicAdd(dst,     ax);
            atomicAdd(dst + 1, ay);
        }
        __syncthreads();
    }
}

// ---------------------------------------------------------------------------
// K_red_out: v = squash(sum of 4 pass-2 partials) -> out. grid 256, 160 thr.
// ---------------------------------------------------------------------------
__global__ __launch_bounds__(160) void k_red_out(float* __restrict__ out)
{
    const int b = blockIdx.x;
    const int t = threadIdx.x;

    float s = 0.f;
#pragma unroll
    for (int k = 0; k < QCH_; ++k)
        s += g_sp2[((size_t)k*B_ + b)*ND_ + t];

    float sq = s*s;
#pragma unroll
    for (int o = 1; o < 16; o <<= 1)
        sq += __shfl_xor_sync(0xffffffffu, sq, o);
    float f = sq / (1.f + sq) / (sqrtf(sq) + 1e-8f);
    out[(size_t)b*ND_ + t] = s * f;
}

// ---------------------------------------------------------------------------
// K2 pass: one routing iteration over a 288-c chunk.
//   PASS 1: prologue computes v1 = squash(0.1*g_s0) (also -> g_v); vcur = v1.
//   PASS 2: prologue computes v2 from g_sp partials; vcur = v1 + v2.
//   logit = u.vcur; coef accumulated in half2 with fp32 drain every 6 iters.
// grid (4 qchunks, 256 b), 256 threads = 8 warps, 4 CTAs/SM.
// lane = g*16+n: g = d-half, n = capsule; 2 chains (c = 2w, 2w+1), 18 iters.
// ---------------------------------------------------------------------------
__device__ __forceinline__ void route_step_h(
    uint4 X, bool act,
    const __half2* __restrict__ vh2, __half2* __restrict__ sh)
{
    unsigned int r[4] = {X.x, X.y, X.z, X.w};
    const __half2* u2 = reinterpret_cast<const __half2*>(r);

    __half2 acc = __hmul2(u2[0], vh2[0]);
    acc = __hfma2(u2[1], vh2[1], acc);
    acc = __hfma2(u2[2], vh2[2], acc);
    acc = __hfma2(u2[3], vh2[3], acc);
    float2 fa = __half22float2(acc);
    float part = fa.x + fa.y;
    float logit = part + __shfl_xor_sync(0xffffffffu, part, 16);

    float e = act ? __expf(logit) : 0.f;
    float ssum = e;
#pragma unroll
    for (int o = 8; o; o >>= 1)
        ssum += __shfl_xor_sync(0xffffffffu, ssum, o);
    float coef = e * __fdividef(1.f, ssum);

    __half2 ch = __float2half2_rn(coef);
    sh[0] = __hfma2(ch, u2[0], sh[0]);
    sh[1] = __hfma2(ch, u2[1], sh[1]);
    sh[2] = __hfma2(ch, u2[2], sh[2]);
    sh[3] = __hfma2(ch, u2[3], sh[3]);
}

template<int PASS>
__global__ __launch_bounds__(256, 4) void k2_pass()
{
    __shared__ float sred[8*ND_];
    __shared__ float vsm[ND_];

    const int  qc = blockIdx.x;
    const int  b  = blockIdx.y;
    const int  t  = threadIdx.x;
    const int  w  = t >> 5;
    const int  l  = t & 31;
    const int  g  = l >> 4;
    const int  n  = l & 15;
    const bool act = (n < N_);

    // prologue: vcur into vsm (plain layout)
    if (PASS == 1) {
        // v1 = squash(0.1 * g_s0)  (g_s0 is p-layout); also publish to g_v
        if (t < ND_) sred[t] = g_s0[(size_t)b*ND_ + t] * 0.1f;
        __syncthreads();
        if (t < ND_) {
            const int g2 = t / 80, rem = t - g2*80, nn = rem >> 3, dd = rem & 7;
            float s = sred[t];
            float sq = 0.f;
#pragma unroll
            for (int gg = 0; gg < 2; ++gg)
#pragma unroll
                for (int d2 = 0; d2 < 8; ++d2) {
                    float v = sred[gg*80 + nn*8 + d2]; sq += v*v;
                }
            float f = sq / (1.f + sq) / (sqrtf(sq) + 1e-8f);
            float v1 = s * f;
            vsm[nn*16 + g2*8 + dd] = v1;
            g_v[(size_t)b*ND_ + nn*16 + g2*8 + dd] = v1;   // plain layout
        }
    } else {
        if (t < ND_) {
            float s = 0.f;
#pragma unroll
            for (int k = 0; k < QCH_; ++k)
                s += g_sp[((size_t)k*B_ + b)*ND_ + t];
            float sq = s*s;
#pragma unroll
            for (int o = 1; o < 16; o <<= 1)
                sq += __shfl_xor_sync(0xffffffffu, sq, o);
            float f = sq / (1.f + sq) / (sqrtf(sq) + 1e-8f);
            vsm[t] = s * f + g_v[(size_t)b*ND_ + t];    // v1 + v2
        }
    }
    __syncthreads();

    __half2 vh2[4];
#pragma unroll
    for (int k = 0; k < 4; ++k) {
        float vx = act ? vsm[n*16 + g*8 + 2*k]     : 0.f;
        float vy = act ? vsm[n*16 + g*8 + 2*k + 1] : 0.f;
        vh2[k] = __floats2half2_rn(vx, vy);
    }

    float sacc[8];
#pragma unroll
    for (int d = 0; d < 8; ++d) sacc[d] = 0.f;

    const unsigned short* uhA =
        g_uhat + (size_t)b*(C_*160) + (size_t)(qc*288 + 2*w)*160 + g*80 + n*8;
    const unsigned short* uhB = uhA + 160;

    uint4 A = make_uint4(0,0,0,0), Bv = make_uint4(0,0,0,0);
    if (act) {
        A  = *reinterpret_cast<const uint4*>(uhA);
        Bv = *reinterpret_cast<const uint4*>(uhB);
    }

#pragma unroll
    for (int blk = 0; blk < 3; ++blk) {
        __half2 sh[4];
        sh[0] = sh[1] = sh[2] = sh[3] = __float2half2_rn(0.f);
#pragma unroll
        for (int j = 0; j < 6; ++j) {
            const int i = blk*6 + j;
            uint4 a = A;
            if (i < 17 && act)
                A = *reinterpret_cast<const uint4*>(uhA + (size_t)(i+1)*16*160);
            route_step_h(a, act, vh2, sh);

            uint4 bb = Bv;
            if (i < 17 && act)
                Bv = *reinterpret_cast<const uint4*>(uhB + (size_t)(i+1)*16*160);
            route_step_h(bb, act, vh2, sh);
        }
        // fp32 drain
#pragma unroll
        for (int k = 0; k < 4; ++k) {
            float2 f = __half22float2(sh[k]);
            sacc[2*k]   += f.x;
            sacc[2*k+1] += f.y;
        }
    }

    if (act) {
#pragma unroll
        for (int d = 0; d < 8; ++d) sred[w*ND_ + n*16 + g*8 + d] = sacc[d];
    }
    __syncthreads();
    if (t < ND_) {
        float a = 0.f;
#pragma unroll
        for (int k = 0; k < 8; ++k) a += sred[k*ND_ + t];
        float* dst = (PASS == 1) ? g_sp : g_sp2;
        dst[((size_t)qc*B_ + b)*ND_ + t] = a;
    }
}

// ---------------------------------------------------------------------------
extern "C" void kernel_launch(void* const* d_in, const int* in_sizes, int n_in,
                              void* d_out, int out_size)
{
    const float* x;
    const float* W;
    if (in_sizes[0] == B_*C_*8) { x = (const float*)d_in[0]; W = (const float*)d_in[1]; }
    else                        { x = (const float*)d_in[1]; W = (const float*)d_in[0]; }
    float* out = (float*)d_out;

    k_zero<<<(B_*ND_ + 1023)/1024, 1024>>>();      // clear s0 accumulator
    k1_gemm<<<dim3(CCH_, 2), 320>>>(x, W);         // 288 CTAs = single wave
    k2_pass<1><<<dim3(QCH_, B_), 256>>>();         // v1 prologue; logit=u.v1 -> g_sp
    k2_pass<2><<<dim3(QCH_, B_), 256>>>();         // v2 prologue; logit=u.(v1+v2) -> g_sp2
    k_red_out<<<B_, 160>>>(out);                   // -> v3 = output
}